// round 7
// baseline (speedup 1.0000x reference)
#include <cuda_runtime.h>
#include <cuda_bf16.h>
#include <math.h>

#define TDEC 200
#define TENC 256
#define NB 128
#define NT 128

// ---------------- device scratch ----------------
__device__ float  d_gipre[(size_t)TDEC * 768 * 64];   // prenet part of att-GRU gates (+bih)
__device__ float  d_pmT [(size_t)64 * 256 * 256];     // processed memory [b][d][te]
__device__ float  d_encT[(size_t)64 * 256 * 256];     // encoder transposed [b][d][te]
__device__ float4 d_wA_ih[256 * 256];                 // att_wih ctx-part gate-packed (r,z,n)
__device__ float4 d_wA_hh[256 * 256];
__device__ float4 d_w1_ih[256 * 256];
__device__ float4 d_w1_hh[256 * 256];
__device__ float4 d_w2_ih[256 * 256];
__device__ float4 d_w2_hh[256 * 256];
__device__ float  d_hA[2][256 * 64];                  // ping-pong states [dim][b]
__device__ float  d_h1[2][256 * 64];
__device__ float  d_h2[2][256 * 64];
__device__ float  d_ctx[256 * 64];
__device__ float  d_q  [256 * 64];
__device__ float  d_dT [256 * 64];
__device__ float  d_d2T[256 * 64];
__device__ float  d_ebuf[64 * 256];
__device__ float  d_Sp[64 * 2];
__device__ float  d_pbuf[(size_t)TDEC * 512 * 64];    // [t][ d3(0:256)|ctx(256:512) ][b]
__device__ unsigned long long g_bar;

__device__ __forceinline__ float dot4(float4 a, float4 b) {
    return a.x*b.x + a.y*b.y + a.z*b.z + a.w*b.w;
}
__device__ __forceinline__ float tanh_fast(float x) {
    float y; asm("tanh.approx.f32 %0, %1;" : "=f"(y) : "f"(x)); return y;
}
__device__ __forceinline__ float sigmoidf_(float x) { return 1.f / (1.f + expf(-x)); }

__device__ __forceinline__ void gbar(unsigned long long& tgt) {
    __syncthreads();
    __threadfence();
    tgt += (unsigned long long)NB;
    if (threadIdx.x == 0) {
        atomicAdd(&g_bar, 1ull);
        while (*((volatile unsigned long long*)&g_bar) < tgt) {}
        __threadfence();   // gpu-scope fence -> L1D invalidate on this SM
    }
    __syncthreads();
}

// ---------------- pack / init ----------------
__global__ void pack_kernel(const float* att_wih, const float* att_whh,
                            const float* g1_wih, const float* g1_whh,
                            const float* g2_wih, const float* g2_whh) {
    int g = blockIdx.x * 256 + threadIdx.x;      // [0, 65536)
    int j = g >> 8, k = g & 255;
    d_wA_ih[g] = make_float4(att_wih[(size_t)j*384 + 128 + k],
                             att_wih[(size_t)(256+j)*384 + 128 + k],
                             att_wih[(size_t)(512+j)*384 + 128 + k], 0.f);
    d_wA_hh[g] = make_float4(att_whh[(size_t)j*256 + k],
                             att_whh[(size_t)(256+j)*256 + k],
                             att_whh[(size_t)(512+j)*256 + k], 0.f);
    d_w1_ih[g] = make_float4(g1_wih[(size_t)j*256 + k],
                             g1_wih[(size_t)(256+j)*256 + k],
                             g1_wih[(size_t)(512+j)*256 + k], 0.f);
    d_w1_hh[g] = make_float4(g1_whh[(size_t)j*256 + k],
                             g1_whh[(size_t)(256+j)*256 + k],
                             g1_whh[(size_t)(512+j)*256 + k], 0.f);
    d_w2_ih[g] = make_float4(g2_wih[(size_t)j*256 + k],
                             g2_wih[(size_t)(256+j)*256 + k],
                             g2_wih[(size_t)(512+j)*256 + k], 0.f);
    d_w2_hh[g] = make_float4(g2_whh[(size_t)j*256 + k],
                             g2_whh[(size_t)(256+j)*256 + k],
                             g2_whh[(size_t)(512+j)*256 + k], 0.f);
    if (g < 256 * 64) {
        d_hA[0][g] = 0.f; d_hA[1][g] = 0.f;
        d_h1[0][g] = 0.f; d_h1[1][g] = 0.f;
        d_h2[0][g] = 0.f; d_h2[1][g] = 0.f;
        d_ctx[g] = 0.f;
    }
    if (g == 0) g_bar = 0ull;
}

// ---------------- pm + encT ----------------
__global__ void pm_kernel(const float* __restrict__ enc, const float* __restrict__ mem_w) {
    size_t g = (size_t)blockIdx.x * 256 + threadIdx.x;   // 64*256*256
    int dd = (int)(g & 255);
    int te = (int)((g >> 8) & 255);
    int bb = (int)(g >> 16);
    const float4* e4 = (const float4*)(enc + ((size_t)bb*256 + te)*256);  // warp-uniform
    const float4* w4 = (const float4*)(mem_w + (size_t)dd*256);           // lane row
    float acc = 0.f;
#pragma unroll 8
    for (int k = 0; k < 64; k++) acc += dot4(e4[k], w4[k]);
    d_pmT[((size_t)bb*256 + dd)*256 + te] = acc;
    d_encT[((size_t)bb*256 + dd)*256 + te] = enc[((size_t)bb*256 + te)*256 + dd];
}

// ---------------- prenet + gipre ----------------
__global__ void prenet_kernel(const float* __restrict__ inputs,
                              const float* __restrict__ w1, const float* __restrict__ b1,
                              const float* __restrict__ w2, const float* __restrict__ b2,
                              const float* __restrict__ att_wih,
                              const float* __restrict__ att_bih) {
    int t = blockIdx.x, b = blockIdx.y, tid = threadIdx.x;
    __shared__ float x[160];
    __shared__ float p1[256];
    __shared__ float p2[128];
    if (tid < 160) x[tid] = (t == 0) ? 0.f : inputs[((size_t)b*TDEC + (t-1))*160 + tid];
    __syncthreads();
    {
        float acc = b1[tid];
        const float* wr = w1 + (size_t)tid*160;
#pragma unroll 8
        for (int i = 0; i < 160; i++) acc += wr[i] * x[i];
        p1[tid] = fmaxf(acc, 0.f);
    }
    __syncthreads();
    if (tid < 128) {
        float acc = b2[tid];
        const float* wr = w2 + (size_t)tid*256;
#pragma unroll 8
        for (int i = 0; i < 256; i++) acc += wr[i] * p1[i];
        p2[tid] = fmaxf(acc, 0.f);
    }
    __syncthreads();
    for (int o = tid; o < 768; o += 256) {
        float acc = att_bih[o];
        const float* wr = att_wih + (size_t)o*384;
#pragma unroll 8
        for (int i = 0; i < 128; i++) acc += wr[i] * p2[i];
        d_gipre[((size_t)t*768 + o)*64 + b] = acc;
    }
}

// ---------------- persistent recurrence ----------------
__global__ void __launch_bounds__(NT, 1)
loop_kernel(const int* __restrict__ memlen,
            const float* __restrict__ att_bhh,
            const float* __restrict__ q_w, const float* __restrict__ v_w,
            const float* __restrict__ proj_w, const float* __restrict__ proj_b,
            const float* __restrict__ g1_bih, const float* __restrict__ g1_bhh,
            const float* __restrict__ g2_bih, const float* __restrict__ g2_bhh,
            float* __restrict__ out) {
    int tid = threadIdx.x, bid = blockIdx.x;
    int gid = bid * NT + tid;                 // [0, 16384)
    int j  = gid >> 6, b  = gid & 63;         // (unit, batch) mapping
    int sb = gid >> 8, ste = gid & 255;       // (batch, te/d) mapping
    unsigned long long tgt = 0;
    float* attn_out = out + 2048000;
    __shared__ float red[NT];
    const int mlen = memlen[sb];

    for (int t = 0; t < TDEC; t++) {
        const float* hAo = d_hA[t & 1];  float* hAn = d_hA[1 - (t & 1)];
        const float* h1o = d_h1[t & 1];  float* h1n = d_h1[1 - (t & 1)];
        const float* h2o = d_h2[t & 1];  float* h2n = d_h2[1 - (t & 1)];

        // ---- Phase A: attention GRU ----
        {
            const float* gp = d_gipre + (size_t)t*768*64;
            float gr = gp[(size_t)j*64 + b];
            float gz = gp[(size_t)(256+j)*64 + b];
            float gn = gp[(size_t)(512+j)*64 + b];
            float hr = att_bhh[j], hz = att_bhh[256+j], hn = att_bhh[512+j];
            const float4* wi = d_wA_ih + j*256;
            const float4* wh = d_wA_hh + j*256;
#pragma unroll 4
            for (int k = 0; k < 256; k++) {
                float4 a = wi[k]; float c = d_ctx[k*64 + b];
                gr += a.x*c; gz += a.y*c; gn += a.z*c;
                float4 w = wh[k]; float h = hAo[k*64 + b];
                hr += w.x*h; hz += w.y*h; hn += w.z*h;
            }
            float hp = hAo[j*64 + b];
            float r = sigmoidf_(gr + hr), z = sigmoidf_(gz + hz);
            float n = tanhf(gn + r*hn);
            hAn[j*64 + b] = (1.f - z)*n + z*hp;
        }
        gbar(tgt);

        // ---- Phase Q ----
        {
            const float4* qw4 = (const float4*)(q_w + (size_t)j*256);
            float acc = 0.f;
#pragma unroll 4
            for (int k = 0; k < 256; k += 4) {
                float4 w = qw4[k >> 2];
                acc += w.x*hAn[k*64+b] + w.y*hAn[(k+1)*64+b]
                     + w.z*hAn[(k+2)*64+b] + w.w*hAn[(k+3)*64+b];
            }
            d_q[j*64 + b] = acc;
        }
        gbar(tgt);

        // ---- Phase SCORE: Bahdanau energies + exp + partial softmax sums ----
        {
            const float* pm = d_pmT + (size_t)sb*256*256 + ste;
            float acc = 0.f;
#pragma unroll 4
            for (int dd = 0; dd < 256; dd++)
                acc += v_w[dd] * tanh_fast(pm[(size_t)dd*256] + d_q[dd*64 + sb]);
            float e = (ste < mlen) ? expf(acc) : 0.f;
            d_ebuf[sb*256 + ste] = e;
            red[tid] = e; __syncthreads();
            for (int s = 64; s > 0; s >>= 1) { if (tid < s) red[tid] += red[tid+s]; __syncthreads(); }
            if (tid == 0) d_Sp[sb*2 + (bid & 1)] = red[0];
        }
        gbar(tgt);

        // ---- Phase CTX: weighted sum of encoder outputs ----
        {
            float inv = 1.f / (d_Sp[sb*2] + d_Sp[sb*2 + 1]);
            const float4* e4 = (const float4*)(d_ebuf + sb*256);
            const float4* m4 = (const float4*)(d_encT + ((size_t)sb*256 + ste)*256);
            float acc = 0.f;
#pragma unroll 8
            for (int i = 0; i < 64; i++) acc += dot4(e4[i], m4[i]);
            acc *= inv;
            d_ctx[ste*64 + sb] = acc;
            d_pbuf[((size_t)t*512 + 256 + ste)*64 + sb] = acc;
        }
        gbar(tgt);

        // ---- Phase PROJ + attention output write ----
        {
            const float4* pw4 = (const float4*)(proj_w + (size_t)j*512);
            float acc = proj_b[j];
#pragma unroll 4
            for (int k = 0; k < 256; k += 4) {
                float4 w = pw4[k >> 2];
                acc += w.x*hAn[k*64+b] + w.y*hAn[(k+1)*64+b]
                     + w.z*hAn[(k+2)*64+b] + w.w*hAn[(k+3)*64+b];
            }
#pragma unroll 4
            for (int k = 0; k < 256; k += 4) {
                float4 w = pw4[(256 + k) >> 2];
                acc += w.x*d_ctx[k*64+b] + w.y*d_ctx[(k+1)*64+b]
                     + w.z*d_ctx[(k+2)*64+b] + w.w*d_ctx[(k+3)*64+b];
            }
            d_dT[j*64 + b] = acc;
            float inv = 1.f / (d_Sp[sb*2] + d_Sp[sb*2 + 1]);
            attn_out[((size_t)sb*TDEC + t)*256 + ste] = d_ebuf[sb*256 + ste] * inv;
        }
        gbar(tgt);

        // ---- Phase GRU1 ----
        {
            float gr = g1_bih[j], gz = g1_bih[256+j], gn = g1_bih[512+j];
            float hr = g1_bhh[j], hz = g1_bhh[256+j], hn = g1_bhh[512+j];
            const float4* wi = d_w1_ih + j*256;
            const float4* wh = d_w1_hh + j*256;
#pragma unroll 4
            for (int k = 0; k < 256; k++) {
                float4 a = wi[k]; float x = d_dT[k*64 + b];
                gr += a.x*x; gz += a.y*x; gn += a.z*x;
                float4 w = wh[k]; float h = h1o[k*64 + b];
                hr += w.x*h; hz += w.y*h; hn += w.z*h;
            }
            float hp = h1o[j*64 + b];
            float r = sigmoidf_(gr + hr), z = sigmoidf_(gz + hz);
            float n = tanhf(gn + r*hn);
            float hv = (1.f - z)*n + z*hp;
            h1n[j*64 + b] = hv;
            d_d2T[j*64 + b] = hv + d_dT[j*64 + b];
        }
        gbar(tgt);

        // ---- Phase GRU2 (no trailing barrier needed) ----
        {
            float gr = g2_bih[j], gz = g2_bih[256+j], gn = g2_bih[512+j];
            float hr = g2_bhh[j], hz = g2_bhh[256+j], hn = g2_bhh[512+j];
            const float4* wi = d_w2_ih + j*256;
            const float4* wh = d_w2_hh + j*256;
#pragma unroll 4
            for (int k = 0; k < 256; k++) {
                float4 a = wi[k]; float x = d_d2T[k*64 + b];
                gr += a.x*x; gz += a.y*x; gn += a.z*x;
                float4 w = wh[k]; float h = h2o[k*64 + b];
                hr += w.x*h; hz += w.y*h; hn += w.z*h;
            }
            float hp = h2o[j*64 + b];
            float r = sigmoidf_(gr + hr), z = sigmoidf_(gz + hz);
            float n = tanhf(gn + r*hn);
            float hv = (1.f - z)*n + z*hp;
            h2n[j*64 + b] = hv;
            d_pbuf[((size_t)t*512 + j)*64 + b] = hv + d_d2T[j*64 + b];
        }
    }
}

// ---------------- output heads ----------------
__global__ void post_kernel(const float* __restrict__ mel_w, const float* __restrict__ mel_b,
                            const float* __restrict__ stop_w, const float* __restrict__ stop_b,
                            float* __restrict__ out) {
    int t = blockIdx.x, tid = threadIdx.x;
    __shared__ __align__(16) float p[512];
    float* stop_out = out + 5324800;
    for (int b = 0; b < 64; b++) {
        __syncthreads();
        p[tid]       = d_pbuf[((size_t)t*512 + tid)*64 + b];
        p[tid + 256] = d_pbuf[((size_t)t*512 + tid + 256)*64 + b];
        __syncthreads();
        if (tid < 160) {
            const float4* w4 = (const float4*)(mel_w + (size_t)tid*512);
            const float4* p4 = (const float4*)p;
            float acc = mel_b[tid];
#pragma unroll 8
            for (int i = 0; i < 128; i++) acc += dot4(w4[i], p4[i]);
            out[((size_t)b*TDEC + t)*160 + tid] = acc;
        } else if (tid == 192) {
            float acc = stop_b[0];
            for (int i = 0; i < 512; i++) acc += stop_w[i] * p[i];
            float s = 1.f / (1.f + expf(-acc));
            stop_out[b*400 + 2*t]     = s;
            stop_out[b*400 + 2*t + 1] = s;
        }
    }
}

extern "C" void kernel_launch(void* const* d_in, const int* in_sizes, int n_in,
                              void* d_out, int out_size) {
    const float* enc      = (const float*)d_in[0];
    const float* inputs   = (const float*)d_in[1];
    const int*   memlen   = (const int*)  d_in[2];
    const float* pre_w1   = (const float*)d_in[3];
    const float* pre_b1   = (const float*)d_in[4];
    const float* pre_w2   = (const float*)d_in[5];
    const float* pre_b2   = (const float*)d_in[6];
    const float* mem_w    = (const float*)d_in[7];
    const float* att_wih  = (const float*)d_in[8];
    const float* att_whh  = (const float*)d_in[9];
    const float* att_bih  = (const float*)d_in[10];
    const float* att_bhh  = (const float*)d_in[11];
    const float* q_w      = (const float*)d_in[12];
    const float* v_w      = (const float*)d_in[13];
    const float* proj_w   = (const float*)d_in[14];
    const float* proj_b   = (const float*)d_in[15];
    const float* g1_wih   = (const float*)d_in[16];
    const float* g1_whh   = (const float*)d_in[17];
    const float* g1_bih   = (const float*)d_in[18];
    const float* g1_bhh   = (const float*)d_in[19];
    const float* g2_wih   = (const float*)d_in[20];
    const float* g2_whh   = (const float*)d_in[21];
    const float* g2_bih   = (const float*)d_in[22];
    const float* g2_bhh   = (const float*)d_in[23];
    const float* mel_w    = (const float*)d_in[24];
    const float* mel_b    = (const float*)d_in[25];
    const float* stop_w   = (const float*)d_in[26];
    const float* stop_b   = (const float*)d_in[27];
    float* out = (float*)d_out;

    pack_kernel<<<256, 256>>>(att_wih, att_whh, g1_wih, g1_whh, g2_wih, g2_whh);
    pm_kernel<<<16384, 256>>>(enc, mem_w);
    prenet_kernel<<<dim3(TDEC, 64), 256>>>(inputs, pre_w1, pre_b1, pre_w2, pre_b2,
                                           att_wih, att_bih);
    loop_kernel<<<NB, NT>>>(memlen, att_bhh, q_w, v_w, proj_w, proj_b,
                            g1_bih, g1_bhh, g2_bih, g2_bhh, out);
    post_kernel<<<TDEC, 256>>>(mel_w, mel_b, stop_w, stop_b, out);
}

// round 8
// speedup vs baseline: 1.6251x; 1.6251x over previous
#include <cuda_runtime.h>
#include <cuda_bf16.h>
#include <math.h>

#define TDEC 200
#define TENC 256
#define NB 128
#define NT 512

// ---------------- device scratch ----------------
__device__ float  d_gipre[(size_t)TDEC * 768 * 64];
__device__ float  d_pmT [(size_t)64 * 256 * 256];     // processed memory [b][d][te]
__device__ float4 d_wA_ih[256 * 256];
__device__ float4 d_wA_hh[256 * 256];
__device__ float4 d_w1_ih[256 * 256];
__device__ float4 d_w1_hh[256 * 256];
__device__ float4 d_w2_ih[256 * 256];
__device__ float4 d_w2_hh[256 * 256];
__device__ float  d_hA[2][256 * 64];
__device__ float  d_h1[2][256 * 64];
__device__ float  d_h2[2][256 * 64];
__device__ float  d_ctx[256 * 64];
__device__ float  d_q  [256 * 64];
__device__ float  d_dT [256 * 64];
__device__ float  d_d2T[256 * 64];
__device__ float  d_ebuf[64 * 256];
__device__ float  d_Sp[64 * 2];
__device__ float  d_pbuf[(size_t)TDEC * 512 * 64];    // [t][ d3(0:256)|ctx(256:512) ][b]
__device__ unsigned long long g_bar;

__device__ __forceinline__ float tanh_fast(float x) {
    float y; asm("tanh.approx.f32 %0, %1;" : "=f"(y) : "f"(x)); return y;
}
__device__ __forceinline__ float sigmoidf_(float x) { return 1.f / (1.f + expf(-x)); }

__device__ __forceinline__ void gbar(unsigned long long& tgt) {
    __syncthreads();
    __threadfence();
    tgt += (unsigned long long)NB;
    if (threadIdx.x == 0) {
        atomicAdd(&g_bar, 1ull);
        while (*((volatile unsigned long long*)&g_bar) < tgt) {}
        __threadfence();
    }
    __syncthreads();
}

__global__ void pack_kernel(const float* att_wih, const float* att_whh,
                            const float* g1_wih, const float* g1_whh,
                            const float* g2_wih, const float* g2_whh) {
    int g = blockIdx.x * 256 + threadIdx.x;
    int j = g >> 8, k = g & 255;
    d_wA_ih[g] = make_float4(att_wih[(size_t)j*384 + 128 + k],
                             att_wih[(size_t)(256+j)*384 + 128 + k],
                             att_wih[(size_t)(512+j)*384 + 128 + k], 0.f);
    d_wA_hh[g] = make_float4(att_whh[(size_t)j*256 + k],
                             att_whh[(size_t)(256+j)*256 + k],
                             att_whh[(size_t)(512+j)*256 + k], 0.f);
    d_w1_ih[g] = make_float4(g1_wih[(size_t)j*256 + k],
                             g1_wih[(size_t)(256+j)*256 + k],
                             g1_wih[(size_t)(512+j)*256 + k], 0.f);
    d_w1_hh[g] = make_float4(g1_whh[(size_t)j*256 + k],
                             g1_whh[(size_t)(256+j)*256 + k],
                             g1_whh[(size_t)(512+j)*256 + k], 0.f);
    d_w2_ih[g] = make_float4(g2_wih[(size_t)j*256 + k],
                             g2_wih[(size_t)(256+j)*256 + k],
                             g2_wih[(size_t)(512+j)*256 + k], 0.f);
    d_w2_hh[g] = make_float4(g2_whh[(size_t)j*256 + k],
                             g2_whh[(size_t)(256+j)*256 + k],
                             g2_whh[(size_t)(512+j)*256 + k], 0.f);
    if (g < 256 * 64) {
        d_hA[0][g] = 0.f; d_hA[1][g] = 0.f;
        d_h1[0][g] = 0.f; d_h1[1][g] = 0.f;
        d_h2[0][g] = 0.f; d_h2[1][g] = 0.f;
        d_ctx[g] = 0.f;
    }
    if (g == 0) g_bar = 0ull;
}

__global__ void pm_kernel(const float* __restrict__ enc, const float* __restrict__ mem_w) {
    size_t g = (size_t)blockIdx.x * 256 + threadIdx.x;
    int dd = (int)(g & 255);
    int te = (int)((g >> 8) & 255);
    int bb = (int)(g >> 16);
    const float4* e4 = (const float4*)(enc + ((size_t)bb*256 + te)*256);
    const float4* w4 = (const float4*)(mem_w + (size_t)dd*256);
    float acc = 0.f;
#pragma unroll 8
    for (int k = 0; k < 64; k++) {
        float4 a = e4[k], w = w4[k];
        acc += a.x*w.x + a.y*w.y + a.z*w.z + a.w*w.w;
    }
    d_pmT[((size_t)bb*256 + dd)*256 + te] = acc;
}

__global__ void prenet_kernel(const float* __restrict__ inputs,
                              const float* __restrict__ w1, const float* __restrict__ b1,
                              const float* __restrict__ w2, const float* __restrict__ b2,
                              const float* __restrict__ att_wih,
                              const float* __restrict__ att_bih) {
    int t = blockIdx.x, b = blockIdx.y, tid = threadIdx.x;
    __shared__ float x[160];
    __shared__ float p1[256];
    __shared__ float p2[128];
    if (tid < 160) x[tid] = (t == 0) ? 0.f : inputs[((size_t)b*TDEC + (t-1))*160 + tid];
    __syncthreads();
    {
        float acc = b1[tid];
        const float* wr = w1 + (size_t)tid*160;
#pragma unroll 8
        for (int i = 0; i < 160; i++) acc += wr[i] * x[i];
        p1[tid] = fmaxf(acc, 0.f);
    }
    __syncthreads();
    if (tid < 128) {
        float acc = b2[tid];
        const float* wr = w2 + (size_t)tid*256;
#pragma unroll 8
        for (int i = 0; i < 256; i++) acc += wr[i] * p1[i];
        p2[tid] = fmaxf(acc, 0.f);
    }
    __syncthreads();
    for (int o = tid; o < 768; o += 256) {
        float acc = att_bih[o];
        const float* wr = att_wih + (size_t)o*384;
#pragma unroll 8
        for (int i = 0; i < 128; i++) acc += wr[i] * p2[i];
        d_gipre[((size_t)t*768 + o)*64 + b] = acc;
    }
}

// tid layout: b = tid&63, jj = (tid>>6)&1, kc = tid>>7 (k-split 4)
__global__ void __launch_bounds__(NT, 1)
loop_kernel(const float* __restrict__ enc,
            const int* __restrict__ memlen,
            const float* __restrict__ att_bhh,
            const float* __restrict__ q_w, const float* __restrict__ v_w,
            const float* __restrict__ proj_w, const float* __restrict__ proj_b,
            const float* __restrict__ g1_bih, const float* __restrict__ g1_bhh,
            const float* __restrict__ g2_bih, const float* __restrict__ g2_bhh,
            float* __restrict__ out) {
    extern __shared__ float smem[];
    float4* w4s   = (float4*)smem;                 // [mat][jj*256+k] : 3072 float4 (48KB)
    float*  qsw   = smem + 3072*4;                 // 512
    float*  projs = qsw + 512;                     // 1024
    float*  p6    = projs + 1024;                  // 512*6
    float*  red   = p6 + 512*6;                    // 512

    const int tid = threadIdx.x, bid = blockIdx.x;
    const int b  = tid & 63;
    const int jj = (tid >> 6) & 1;
    const int kc = tid >> 7;
    const int k0 = kc * 64;
    const int jf = bid * 2 + ((tid >> 6) & 1);     // finalize row (valid tid<128)
    const int sb  = bid >> 1;
    const int ste = ((bid & 1) << 7) + (tid & 127);
    const int cc  = tid >> 7;

    {   // stage this CTA's weight rows into SMEM
        int src = (bid*2 + (tid >> 8))*256 + (tid & 255);
        w4s[0*512 + tid] = d_wA_ih[src];
        w4s[1*512 + tid] = d_wA_hh[src];
        w4s[2*512 + tid] = d_w1_ih[src];
        w4s[3*512 + tid] = d_w1_hh[src];
        w4s[4*512 + tid] = d_w2_ih[src];
        w4s[5*512 + tid] = d_w2_hh[src];
        qsw[tid] = q_w[src];
        projs[tid]       = proj_w[(size_t)(bid*2 + (tid>>9))*512 + (tid & 511)];
        projs[tid + 512] = proj_w[(size_t)(bid*2 + 1)*512 + (tid & 511)];
    }
    __syncthreads();

    unsigned long long tgt = 0;
    float* attn_out = out + 2048000;
    const int mlen = memlen[sb];

    for (int t = 0; t < TDEC; t++) {
        const float* hAo = d_hA[t & 1];  float* hAn = d_hA[1 - (t & 1)];
        const float* h1o = d_h1[t & 1];  float* h1n = d_h1[1 - (t & 1)];
        const float* h2o = d_h2[t & 1];  float* h2n = d_h2[1 - (t & 1)];

        // ---- Phase A: attention GRU ----
        {
            const float4* wi = w4s + 0*512 + jj*256;
            const float4* wh = w4s + 1*512 + jj*256;
            float gr=0,gz=0,gn=0,hr=0,hz=0,hn=0;
#pragma unroll 8
            for (int kk = 0; kk < 64; kk++) {
                int k = k0 + kk;
                float4 a = wi[k]; float c = d_ctx[k*64 + b];
                gr += a.x*c; gz += a.y*c; gn += a.z*c;
                float4 w = wh[k]; float h = hAo[k*64 + b];
                hr += w.x*h; hz += w.y*h; hn += w.z*h;
            }
            float* pp = p6 + tid*6;
            pp[0]=gr; pp[1]=gz; pp[2]=gn; pp[3]=hr; pp[4]=hz; pp[5]=hn;
            __syncthreads();
            if (tid < 128) {
                float a0=0,a1=0,a2=0,a3=0,a4=0,a5=0;
#pragma unroll
                for (int c4 = 0; c4 < 4; c4++) {
                    float* q = p6 + (tid + 128*c4)*6;
                    a0+=q[0]; a1+=q[1]; a2+=q[2]; a3+=q[3]; a4+=q[4]; a5+=q[5];
                }
                const float* gp = d_gipre + (size_t)t*768*64;
                float gr2 = a0 + gp[(size_t)jf*64 + b];
                float gz2 = a1 + gp[(size_t)(256+jf)*64 + b];
                float gn2 = a2 + gp[(size_t)(512+jf)*64 + b];
                float hr2 = a3 + att_bhh[jf], hz2 = a4 + att_bhh[256+jf], hn2 = a5 + att_bhh[512+jf];
                float hp = hAo[jf*64 + b];
                float r = sigmoidf_(gr2 + hr2), z = sigmoidf_(gz2 + hz2);
                float n = tanhf(gn2 + r*hn2);
                hAn[jf*64 + b] = (1.f - z)*n + z*hp;
            }
        }
        gbar(tgt);

        // ---- Phase Q ----
        {
            const float* qw = qsw + jj*256;
            float acc = 0.f;
#pragma unroll 8
            for (int kk = 0; kk < 64; kk++) {
                int k = k0 + kk;
                acc += qw[k] * hAn[k*64 + b];
            }
            red[tid] = acc;
            __syncthreads();
            if (tid < 128)
                d_q[jf*64 + b] = red[tid] + red[tid+128] + red[tid+256] + red[tid+384];
        }
        gbar(tgt);

        // ---- Phase SCORE ----
        {
            const float* pm = d_pmT + (size_t)sb*256*256 + ste;
            float acc = 0.f;
            int d0 = cc * 64;
#pragma unroll 4
            for (int i = 0; i < 64; i++) {
                int dd = d0 + i;
                acc += v_w[dd] * tanh_fast(pm[(size_t)dd*256] + d_q[dd*64 + sb]);
            }
            red[tid] = acc;
            __syncthreads();
            if (tid < 128) {
                float s = red[tid] + red[tid+128] + red[tid+256] + red[tid+384];
                float e = (ste < mlen) ? expf(s) : 0.f;
                d_ebuf[sb*256 + ste] = e;
                p6[tid] = e;
            }
            __syncthreads();
            for (int s = 64; s > 0; s >>= 1) {
                if (tid < s) p6[tid] += p6[tid + s];
                __syncthreads();
            }
            if (tid == 0) d_Sp[sb*2 + (bid & 1)] = p6[0];
        }
        gbar(tgt);

        // ---- Phase CTX: ctx[b][d] = (1/S) * sum_te e[te] * enc[b][te][d] ----
        {
            int d = ste;
            float acc = 0.f;
            int t0 = cc * 64;
#pragma unroll 4
            for (int i = 0; i < 64; i++) {
                int te = t0 + i;
                acc += d_ebuf[sb*256 + te] * enc[((size_t)sb*256 + te)*256 + d];
            }
            red[tid] = acc;
            __syncthreads();
            if (tid < 128) {
                float inv = 1.f / (d_Sp[sb*2] + d_Sp[sb*2 + 1]);
                float v = (red[tid] + red[tid+128] + red[tid+256] + red[tid+384]) * inv;
                d_ctx[d*64 + sb] = v;
                d_pbuf[((size_t)t*512 + 256 + d)*64 + sb] = v;
            }
        }
        gbar(tgt);

        // ---- Phase PROJ + attention-weights output ----
        {
            const float* pw = projs + jj*512;
            float acc = 0.f;
            int p0 = kc * 128;
#pragma unroll 8
            for (int kk = 0; kk < 128; kk++) {
                int k = p0 + kk;
                float x = (k < 256) ? hAn[k*64 + b] : d_ctx[(k-256)*64 + b];
                acc += pw[k] * x;
            }
            red[tid] = acc;
            // attention output write (independent of reduction)
            if (tid < 128) {
                float inv = 1.f / (d_Sp[sb*2] + d_Sp[sb*2 + 1]);
                attn_out[((size_t)sb*TDEC + t)*256 + ste] = d_ebuf[sb*256 + ste] * inv;
            }
            __syncthreads();
            if (tid < 128)
                d_dT[jf*64 + b] = proj_b[jf] +
                    red[tid] + red[tid+128] + red[tid+256] + red[tid+384];
        }
        gbar(tgt);

        // ---- Phase GRU1 ----
        {
            const float4* wi = w4s + 2*512 + jj*256;
            const float4* wh = w4s + 3*512 + jj*256;
            float gr=0,gz=0,gn=0,hr=0,hz=0,hn=0;
#pragma unroll 8
            for (int kk = 0; kk < 64; kk++) {
                int k = k0 + kk;
                float4 a = wi[k]; float x = d_dT[k*64 + b];
                gr += a.x*x; gz += a.y*x; gn += a.z*x;
                float4 w = wh[k]; float h = h1o[k*64 + b];
                hr += w.x*h; hz += w.y*h; hn += w.z*h;
            }
            float* pp = p6 + tid*6;
            pp[0]=gr; pp[1]=gz; pp[2]=gn; pp[3]=hr; pp[4]=hz; pp[5]=hn;
            __syncthreads();
            if (tid < 128) {
                float a0=0,a1=0,a2=0,a3=0,a4=0,a5=0;
#pragma unroll
                for (int c4 = 0; c4 < 4; c4++) {
                    float* q = p6 + (tid + 128*c4)*6;
                    a0+=q[0]; a1+=q[1]; a2+=q[2]; a3+=q[3]; a4+=q[4]; a5+=q[5];
                }
                float gr2 = a0 + g1_bih[jf], gz2 = a1 + g1_bih[256+jf], gn2 = a2 + g1_bih[512+jf];
                float hr2 = a3 + g1_bhh[jf], hz2 = a4 + g1_bhh[256+jf], hn2 = a5 + g1_bhh[512+jf];
                float hp = h1o[jf*64 + b];
                float r = sigmoidf_(gr2 + hr2), z = sigmoidf_(gz2 + hz2);
                float n = tanhf(gn2 + r*hn2);
                float hv = (1.f - z)*n + z*hp;
                h1n[jf*64 + b] = hv;
                d_d2T[jf*64 + b] = hv + d_dT[jf*64 + b];
            }
        }
        gbar(tgt);

        // ---- Phase GRU2 (no trailing global barrier) ----
        {
            const float4* wi = w4s + 4*512 + jj*256;
            const float4* wh = w4s + 5*512 + jj*256;
            float gr=0,gz=0,gn=0,hr=0,hz=0,hn=0;
#pragma unroll 8
            for (int kk = 0; kk < 64; kk++) {
                int k = k0 + kk;
                float4 a = wi[k]; float x = d_d2T[k*64 + b];
                gr += a.x*x; gz += a.y*x; gn += a.z*x;
                float4 w = wh[k]; float h = h2o[k*64 + b];
                hr += w.x*h; hz += w.y*h; hn += w.z*h;
            }
            float* pp = p6 + tid*6;
            pp[0]=gr; pp[1]=gz; pp[2]=gn; pp[3]=hr; pp[4]=hz; pp[5]=hn;
            __syncthreads();
            if (tid < 128) {
                float a0=0,a1=0,a2=0,a3=0,a4=0,a5=0;
#pragma unroll
                for (int c4 = 0; c4 < 4; c4++) {
                    float* q = p6 + (tid + 128*c4)*6;
                    a0+=q[0]; a1+=q[1]; a2+=q[2]; a3+=q[3]; a4+=q[4]; a5+=q[5];
                }
                float gr2 = a0 + g2_bih[jf], gz2 = a1 + g2_bih[256+jf], gn2 = a2 + g2_bih[512+jf];
                float hr2 = a3 + g2_bhh[jf], hz2 = a4 + g2_bhh[256+jf], hn2 = a5 + g2_bhh[512+jf];
                float hp = h2o[jf*64 + b];
                float r = sigmoidf_(gr2 + hr2), z = sigmoidf_(gz2 + hz2);
                float n = tanhf(gn2 + r*hn2);
                float hv = (1.f - z)*n + z*hp;
                h2n[jf*64 + b] = hv;
                d_pbuf[((size_t)t*512 + jf)*64 + b] = hv + d_d2T[jf*64 + b];
            }
            __syncthreads();   // protect p6 reuse at next iteration's Phase A
        }
    }
}

__global__ void post_kernel(const float* __restrict__ mel_w, const float* __restrict__ mel_b,
                            const float* __restrict__ stop_w, const float* __restrict__ stop_b,
                            float* __restrict__ out) {
    int t = blockIdx.x, tid = threadIdx.x;
    __shared__ __align__(16) float p[512];
    float* stop_out = out + 5324800;
    for (int b = 0; b < 64; b++) {
        __syncthreads();
        p[tid]       = d_pbuf[((size_t)t*512 + tid)*64 + b];
        p[tid + 256] = d_pbuf[((size_t)t*512 + tid + 256)*64 + b];
        __syncthreads();
        if (tid < 160) {
            const float4* w4 = (const float4*)(mel_w + (size_t)tid*512);
            const float4* p4 = (const float4*)p;
            float acc = mel_b[tid];
#pragma unroll 8
            for (int i = 0; i < 128; i++) {
                float4 a = w4[i], x = p4[i];
                acc += a.x*x.x + a.y*x.y + a.z*x.z + a.w*x.w;
            }
            out[((size_t)b*TDEC + t)*160 + tid] = acc;
        } else if (tid == 192) {
            float acc = stop_b[0];
            for (int i = 0; i < 512; i++) acc += stop_w[i] * p[i];
            float s = 1.f / (1.f + expf(-acc));
            stop_out[b*400 + 2*t]     = s;
            stop_out[b*400 + 2*t + 1] = s;
        }
    }
}

extern "C" void kernel_launch(void* const* d_in, const int* in_sizes, int n_in,
                              void* d_out, int out_size) {
    const float* enc      = (const float*)d_in[0];
    const float* inputs   = (const float*)d_in[1];
    const int*   memlen   = (const int*)  d_in[2];
    const float* pre_w1   = (const float*)d_in[3];
    const float* pre_b1   = (const float*)d_in[4];
    const float* pre_w2   = (const float*)d_in[5];
    const float* pre_b2   = (const float*)d_in[6];
    const float* mem_w    = (const float*)d_in[7];
    const float* att_wih  = (const float*)d_in[8];
    const float* att_whh  = (const float*)d_in[9];
    const float* att_bih  = (const float*)d_in[10];
    const float* att_bhh  = (const float*)d_in[11];
    const float* q_w      = (const float*)d_in[12];
    const float* v_w      = (const float*)d_in[13];
    const float* proj_w   = (const float*)d_in[14];
    const float* proj_b   = (const float*)d_in[15];
    const float* g1_wih   = (const float*)d_in[16];
    const float* g1_whh   = (const float*)d_in[17];
    const float* g1_bih   = (const float*)d_in[18];
    const float* g1_bhh   = (const float*)d_in[19];
    const float* g2_wih   = (const float*)d_in[20];
    const float* g2_whh   = (const float*)d_in[21];
    const float* g2_bih   = (const float*)d_in[22];
    const float* g2_bhh   = (const float*)d_in[23];
    const float* mel_w    = (const float*)d_in[24];
    const float* mel_b    = (const float*)d_in[25];
    const float* stop_w   = (const float*)d_in[26];
    const float* stop_b   = (const float*)d_in[27];
    float* out = (float*)d_out;

    static int smem_set = 0;
    if (!smem_set) {
        cudaFuncSetAttribute(loop_kernel, cudaFuncAttributeMaxDynamicSharedMemorySize,
                             (3072*4 + 512 + 1024 + 512*6 + 512) * (int)sizeof(float));
        smem_set = 1;
    }
    int smem_bytes = (3072*4 + 512 + 1024 + 512*6 + 512) * (int)sizeof(float);

    pack_kernel<<<256, 256>>>(att_wih, att_whh, g1_wih, g1_whh, g2_wih, g2_whh);
    pm_kernel<<<16384, 256>>>(enc, mem_w);
    prenet_kernel<<<dim3(TDEC, 64), 256>>>(inputs, pre_w1, pre_b1, pre_w2, pre_b2,
                                           att_wih, att_bih);
    loop_kernel<<<NB, NT, smem_bytes>>>(enc, memlen, att_bhh, q_w, v_w, proj_w, proj_b,
                                        g1_bih, g1_bhh, g2_bih, g2_bhh, out);
    post_kernel<<<TDEC, 256>>>(mel_w, mel_b, stop_w, stop_b, out);
}

// round 9
// speedup vs baseline: 1.8703x; 1.1509x over previous
#include <cuda_runtime.h>
#include <cuda_bf16.h>
#include <math.h>

#define TDEC 200
#define TENC 256
#define NB 128
#define NT 1024

// ---------------- device scratch ----------------
__device__ float  d_gipre[(size_t)TDEC * 768 * 64];
__device__ float  d_pmT [(size_t)64 * 256 * 256];     // processed memory [b][d][te]
__device__ float4 d_wA_ih[256 * 256];                 // gate-packed (r,z,n)
__device__ float4 d_wA_hh[256 * 256];
__device__ float4 d_w1_ih[256 * 256];
__device__ float4 d_w1_hh[256 * 256];
__device__ float4 d_w2_ih[256 * 256];
__device__ float4 d_w2_hh[256 * 256];
__device__ float  d_hA[2][256 * 64];                  // ping-pong states [dim][b]
__device__ float  d_h1[2][256 * 64];
__device__ float  d_h2[2][256 * 64];
__device__ float  d_ctx[256 * 64];
__device__ float  d_qT [64 * 256];                    // q transposed [b][d]
__device__ float  d_dT [256 * 64];
__device__ float  d_d2T[256 * 64];
__device__ float  d_ebuf[64 * 256];
__device__ float  d_Sp[64 * 2];
__device__ float  d_pbuf[(size_t)TDEC * 512 * 64];    // [t][ d3(0:256)|ctx(256:512) ][b]
__device__ unsigned long long g_bar;

__device__ __forceinline__ float tanh_fast(float x) {
    float y; asm("tanh.approx.f32 %0, %1;" : "=f"(y) : "f"(x)); return y;
}
__device__ __forceinline__ float sigmoidf_(float x) { return 1.f / (1.f + expf(-x)); }

__device__ __forceinline__ void gbar(unsigned long long& tgt) {
    __syncthreads();
    __threadfence();
    tgt += (unsigned long long)NB;
    if (threadIdx.x == 0) {
        atomicAdd(&g_bar, 1ull);
        while (*((volatile unsigned long long*)&g_bar) < tgt) {}
        __threadfence();
    }
    __syncthreads();
}

__global__ void pack_kernel(const float* att_wih, const float* att_whh,
                            const float* g1_wih, const float* g1_whh,
                            const float* g2_wih, const float* g2_whh) {
    int g = blockIdx.x * 256 + threadIdx.x;
    int j = g >> 8, k = g & 255;
    d_wA_ih[g] = make_float4(att_wih[(size_t)j*384 + 128 + k],
                             att_wih[(size_t)(256+j)*384 + 128 + k],
                             att_wih[(size_t)(512+j)*384 + 128 + k], 0.f);
    d_wA_hh[g] = make_float4(att_whh[(size_t)j*256 + k],
                             att_whh[(size_t)(256+j)*256 + k],
                             att_whh[(size_t)(512+j)*256 + k], 0.f);
    d_w1_ih[g] = make_float4(g1_wih[(size_t)j*256 + k],
                             g1_wih[(size_t)(256+j)*256 + k],
                             g1_wih[(size_t)(512+j)*256 + k], 0.f);
    d_w1_hh[g] = make_float4(g1_whh[(size_t)j*256 + k],
                             g1_whh[(size_t)(256+j)*256 + k],
                             g1_whh[(size_t)(512+j)*256 + k], 0.f);
    d_w2_ih[g] = make_float4(g2_wih[(size_t)j*256 + k],
                             g2_wih[(size_t)(256+j)*256 + k],
                             g2_wih[(size_t)(512+j)*256 + k], 0.f);
    d_w2_hh[g] = make_float4(g2_whh[(size_t)j*256 + k],
                             g2_whh[(size_t)(256+j)*256 + k],
                             g2_whh[(size_t)(512+j)*256 + k], 0.f);
    if (g < 256 * 64) {
        d_hA[0][g] = 0.f; d_hA[1][g] = 0.f;
        d_h1[0][g] = 0.f; d_h1[1][g] = 0.f;
        d_h2[0][g] = 0.f; d_h2[1][g] = 0.f;
        d_ctx[g] = 0.f;
    }
    if (g == 0) g_bar = 0ull;
}

__global__ void pm_kernel(const float* __restrict__ enc, const float* __restrict__ mem_w) {
    size_t g = (size_t)blockIdx.x * 256 + threadIdx.x;
    int dd = (int)(g & 255);
    int te = (int)((g >> 8) & 255);
    int bb = (int)(g >> 16);
    const float4* e4 = (const float4*)(enc + ((size_t)bb*256 + te)*256);
    const float4* w4 = (const float4*)(mem_w + (size_t)dd*256);
    float acc = 0.f;
#pragma unroll 8
    for (int k = 0; k < 64; k++) {
        float4 a = e4[k], w = w4[k];
        acc += a.x*w.x + a.y*w.y + a.z*w.z + a.w*w.w;
    }
    d_pmT[((size_t)bb*256 + dd)*256 + te] = acc;
}

__global__ void prenet_kernel(const float* __restrict__ inputs,
                              const float* __restrict__ w1, const float* __restrict__ b1,
                              const float* __restrict__ w2, const float* __restrict__ b2,
                              const float* __restrict__ att_wih,
                              const float* __restrict__ att_bih) {
    int t = blockIdx.x, b = blockIdx.y, tid = threadIdx.x;
    __shared__ float x[160];
    __shared__ float p1[256];
    __shared__ float p2[128];
    if (tid < 160) x[tid] = (t == 0) ? 0.f : inputs[((size_t)b*TDEC + (t-1))*160 + tid];
    __syncthreads();
    {
        float acc = b1[tid];
        const float* wr = w1 + (size_t)tid*160;
#pragma unroll 8
        for (int i = 0; i < 160; i++) acc += wr[i] * x[i];
        p1[tid] = fmaxf(acc, 0.f);
    }
    __syncthreads();
    if (tid < 128) {
        float acc = b2[tid];
        const float* wr = w2 + (size_t)tid*256;
#pragma unroll 8
        for (int i = 0; i < 256; i++) acc += wr[i] * p1[i];
        p2[tid] = fmaxf(acc, 0.f);
    }
    __syncthreads();
    for (int o = tid; o < 768; o += 256) {
        float acc = att_bih[o];
        const float* wr = att_wih + (size_t)o*384;
#pragma unroll 8
        for (int i = 0; i < 128; i++) acc += wr[i] * p2[i];
        d_gipre[((size_t)t*768 + o)*64 + b] = acc;
    }
}

// tid layout: b2 = tid&31 (batch pair), jj = bit5, kc = tid>>6 (16 k-chunks of 16)
__global__ void __launch_bounds__(NT, 1)
loop_kernel(const float* __restrict__ enc,
            const int* __restrict__ memlen,
            const float* __restrict__ att_bhh,
            const float* __restrict__ q_w, const float* __restrict__ v_w,
            const float* __restrict__ proj_w, const float* __restrict__ proj_b,
            const float* __restrict__ g1_bih, const float* __restrict__ g1_bhh,
            const float* __restrict__ g2_bih, const float* __restrict__ g2_bhh,
            float* __restrict__ out) {
    extern __shared__ float smem[];
    float4* w4s   = (float4*)smem;            // 3072 float4 (mats 0..5, 512 each)
    float*  qsw   = smem + 12288;             // 512
    float*  projs = smem + 12800;             // 1024
    float*  qs    = smem + 13824;             // 256
    float*  vs    = smem + 14080;             // 256
    float*  es    = smem + 14336;             // 256
    float*  p6    = smem + 14592;             // 13056 (stride-17 partials)
    float*  red   = p6 + 8192;                // small reduce scratch (inside p6 tail)

    const int tid = threadIdx.x, bid = blockIdx.x;
    const int b2 = tid & 31;
    const int jj = (tid >> 5) & 1;
    const int kc = tid >> 6;                  // 0..15
    const int bb = b2 * 2;
    const int fb = tid & 63;                  // finalize (tid<128): batch
    const int fjj = (tid >> 6) & 1;
    const int jf = bid * 2 + fjj;             // finalize row
    const int sb  = bid >> 1;
    const int ste = ((bid & 1) << 7) + (tid & 127);
    const int dc  = tid >> 7;                 // 0..7

    {   // stage weights
        if (tid < 512) {
            int src = (bid*2 + (tid >> 8))*256 + (tid & 255);
            w4s[0*512 + tid] = d_wA_ih[src];
            w4s[1*512 + tid] = d_wA_hh[src];
            w4s[2*512 + tid] = d_w1_ih[src];
            w4s[3*512 + tid] = d_w1_hh[src];
            w4s[4*512 + tid] = d_w2_ih[src];
            w4s[5*512 + tid] = d_w2_hh[src];
            qsw[tid] = q_w[src];
        }
        projs[tid] = proj_w[(size_t)(bid*2 + (tid >> 9))*512 + (tid & 511)];
        if (tid < 256) vs[tid] = v_w[tid];
    }
    __syncthreads();

    unsigned long long tgt = 0;
    float* attn_out = out + 2048000;
    const int mlen = memlen[sb];
    // recurrent per-(jf,fb) scalars carried in finalize-thread registers
    float hA_prev = 0.f, h1_prev = 0.f, h2_prev = 0.f, dT_val = 0.f, d2T_val = 0.f;

    for (int t = 0; t < TDEC; t++) {
        const float* hAo = d_hA[t & 1];  float* hAn = d_hA[1 - (t & 1)];
        const float* h1o = d_h1[t & 1];  float* h1n = d_h1[1 - (t & 1)];
        const float* h2o = d_h2[t & 1];  float* h2n = d_h2[1 - (t & 1)];

        // ---- Phase A: attention GRU ----
        {
            const float4* wi = w4s + jj*256;
            const float4* wh = w4s + 512 + jj*256;
            const float2* c2 = (const float2*)d_ctx;
            const float2* h2v = (const float2*)hAo;
            float irA=0,izA=0,inA=0,hrA=0,hzA=0,hnA=0;
            float irB=0,izB=0,inB=0,hrB=0,hzB=0,hnB=0;
            int k = kc*16;
#pragma unroll
            for (int kk = 0; kk < 16; kk++, k++) {
                float4 a = wi[k]; float2 c = c2[k*32 + b2];
                irA += a.x*c.x; izA += a.y*c.x; inA += a.z*c.x;
                irB += a.x*c.y; izB += a.y*c.y; inB += a.z*c.y;
                float4 w = wh[k]; float2 h = h2v[k*32 + b2];
                hrA += w.x*h.x; hzA += w.y*h.x; hnA += w.z*h.x;
                hrB += w.x*h.y; hzB += w.y*h.y; hnB += w.z*h.y;
            }
            int ob = (jj*384 + bb)*17 + kc;   // + g*1088 (+17 for lane 1)
            p6[ob + 0*1088] = irA; p6[ob + 0*1088 + 17] = irB;
            p6[ob + 1*1088] = izA; p6[ob + 1*1088 + 17] = izB;
            p6[ob + 2*1088] = inA; p6[ob + 2*1088 + 17] = inB;
            p6[ob + 3*1088] = hrA; p6[ob + 3*1088 + 17] = hrB;
            p6[ob + 4*1088] = hzA; p6[ob + 4*1088 + 17] = hzB;
            p6[ob + 5*1088] = hnA; p6[ob + 5*1088 + 17] = hnB;
            __syncthreads();
            if (tid < 128) {
                float s0=0,s1=0,s2=0,s3=0,s4=0,s5=0;
                int base = (fjj*384 + fb)*17;
#pragma unroll
                for (int q = 0; q < 16; q++) {
                    s0 += p6[base + q];          s1 += p6[base + 1088 + q];
                    s2 += p6[base + 2176 + q];   s3 += p6[base + 3264 + q];
                    s4 += p6[base + 4352 + q];   s5 += p6[base + 5440 + q];
                }
                const float* gp = d_gipre + (size_t)t*768*64;
                float gr = s0 + gp[(size_t)jf*64 + fb];
                float gz = s1 + gp[(size_t)(256+jf)*64 + fb];
                float gn = s2 + gp[(size_t)(512+jf)*64 + fb];
                float hr = s3 + att_bhh[jf], hz = s4 + att_bhh[256+jf], hn = s5 + att_bhh[512+jf];
                float r = sigmoidf_(gr + hr), z = sigmoidf_(gz + hz);
                float n = tanhf(gn + r*hn);
                hA_prev = (1.f - z)*n + z*hA_prev;
                hAn[jf*64 + fb] = hA_prev;
            }
        }
        gbar(tgt);

        // ---- Phase Q ----
        {
            const float* qw = qsw + jj*256;
            const float2* h2v = (const float2*)hAn;
            float aA = 0.f, aB = 0.f;
            int k = kc*16;
#pragma unroll
            for (int kk = 0; kk < 16; kk++, k++) {
                float w = qw[k]; float2 h = h2v[k*32 + b2];
                aA += w*h.x; aB += w*h.y;
            }
            int ob = (jj*64 + bb)*17 + kc;
            p6[ob] = aA; p6[ob + 17] = aB;
            __syncthreads();
            if (tid < 128) {
                float s = 0.f;
                int base = tid*17;
#pragma unroll
                for (int q = 0; q < 16; q++) s += p6[base + q];
                d_qT[fb*256 + jf] = s;
            }
        }
        gbar(tgt);

        // ---- Phase SCORE ----
        {
            if (tid < 256) qs[tid] = d_qT[sb*256 + tid];
            __syncthreads();
            const float* pm = d_pmT + ((size_t)sb*256)*256 + ste;
            float acc = 0.f;
            int dd = dc*32;
#pragma unroll 8
            for (int i = 0; i < 32; i++, dd++)
                acc += vs[dd] * tanh_fast(pm[(size_t)dd*256] + qs[dd]);
            p6[(tid & 127)*9 + dc] = acc;
            __syncthreads();
            if (tid < 128) {
                float s = 0.f;
#pragma unroll
                for (int q = 0; q < 8; q++) s += p6[tid*9 + q];
                float e = (ste < mlen) ? expf(s) : 0.f;
                d_ebuf[sb*256 + ste] = e;
                red[tid] = e;
            }
            __syncthreads();
            if (tid < 32) {
                float s = red[tid] + red[tid+32] + red[tid+64] + red[tid+96];
#pragma unroll
                for (int off = 16; off; off >>= 1) s += __shfl_down_sync(0xffffffff, s, off);
                if (tid == 0) d_Sp[sb*2 + (bid & 1)] = s;
            }
        }
        gbar(tgt);

        // ---- Phase CTX ----
        {
            if (tid < 256) es[tid] = d_ebuf[sb*256 + tid];
            __syncthreads();
            int d = ((bid & 1) << 7) + (tid & 127);
            const float* ec = enc + (size_t)sb*256*256 + d;
            float acc = 0.f;
            int te = dc*32;
#pragma unroll 8
            for (int i = 0; i < 32; i++, te++)
                acc += es[te] * ec[(size_t)te*256];
            p6[(tid & 127)*9 + dc] = acc;
            __syncthreads();
            if (tid < 128) {
                float inv = 1.f / (d_Sp[sb*2] + d_Sp[sb*2 + 1]);
                float s = 0.f;
#pragma unroll
                for (int q = 0; q < 8; q++) s += p6[tid*9 + q];
                s *= inv;
                int d2 = ((bid & 1) << 7) + tid;
                d_ctx[d2*64 + sb] = s;
                d_pbuf[((size_t)t*512 + 256 + d2)*64 + sb] = s;
                attn_out[((size_t)sb*TDEC + t)*256 + d2] = es[d2] * inv;
            }
        }
        gbar(tgt);

        // ---- Phase PROJ ----
        {
            const float* pw = projs + jj*512;
            const float2* src = (kc < 8) ? (const float2*)hAn : (const float2*)d_ctx;
            int k0 = kc*32;
            int koff = (kc < 8) ? k0 : (k0 - 256);
            float aA = 0.f, aB = 0.f;
#pragma unroll 8
            for (int i = 0; i < 32; i++) {
                float w = pw[k0 + i];
                float2 x = src[(koff + i)*32 + b2];
                aA += w*x.x; aB += w*x.y;
            }
            int ob = (jj*64 + bb)*17 + kc;
            p6[ob] = aA; p6[ob + 17] = aB;
            __syncthreads();
            if (tid < 128) {
                float s = proj_b[jf];
                int base = tid*17;
#pragma unroll
                for (int q = 0; q < 16; q++) s += p6[base + q];
                dT_val = s;
                d_dT[jf*64 + fb] = s;
            }
        }
        gbar(tgt);

        // ---- Phase GRU1 ----
        {
            const float4* wi = w4s + 1024 + jj*256;
            const float4* wh = w4s + 1536 + jj*256;
            const float2* x2 = (const float2*)d_dT;
            const float2* h2v = (const float2*)h1o;
            float irA=0,izA=0,inA=0,hrA=0,hzA=0,hnA=0;
            float irB=0,izB=0,inB=0,hrB=0,hzB=0,hnB=0;
            int k = kc*16;
#pragma unroll
            for (int kk = 0; kk < 16; kk++, k++) {
                float4 a = wi[k]; float2 x = x2[k*32 + b2];
                irA += a.x*x.x; izA += a.y*x.x; inA += a.z*x.x;
                irB += a.x*x.y; izB += a.y*x.y; inB += a.z*x.y;
                float4 w = wh[k]; float2 h = h2v[k*32 + b2];
                hrA += w.x*h.x; hzA += w.y*h.x; hnA += w.z*h.x;
                hrB += w.x*h.y; hzB += w.y*h.y; hnB += w.z*h.y;
            }
            int ob = (jj*384 + bb)*17 + kc;
            p6[ob + 0*1088] = irA; p6[ob + 0*1088 + 17] = irB;
            p6[ob + 1*1088] = izA; p6[ob + 1*1088 + 17] = izB;
            p6[ob + 2*1088] = inA; p6[ob + 2*1088 + 17] = inB;
            p6[ob + 3*1088] = hrA; p6[ob + 3*1088 + 17] = hrB;
            p6[ob + 4*1088] = hzA; p6[ob + 4*1088 + 17] = hzB;
            p6[ob + 5*1088] = hnA; p6[ob + 5*1088 + 17] = hnB;
            __syncthreads();
            if (tid < 128) {
                float s0=0,s1=0,s2=0,s3=0,s4=0,s5=0;
                int base = (fjj*384 + fb)*17;
#pragma unroll
                for (int q = 0; q < 16; q++) {
                    s0 += p6[base + q];          s1 += p6[base + 1088 + q];
                    s2 += p6[base + 2176 + q];   s3 += p6[base + 3264 + q];
                    s4 += p6[base + 4352 + q];   s5 += p6[base + 5440 + q];
                }
                float gr = s0 + g1_bih[jf], gz = s1 + g1_bih[256+jf], gn = s2 + g1_bih[512+jf];
                float hr = s3 + g1_bhh[jf], hz = s4 + g1_bhh[256+jf], hn = s5 + g1_bhh[512+jf];
                float r = sigmoidf_(gr + hr), z = sigmoidf_(gz + hz);
                float n = tanhf(gn + r*hn);
                h1_prev = (1.f - z)*n + z*h1_prev;
                h1n[jf*64 + fb] = h1_prev;
                d2T_val = h1_prev + dT_val;
                d_d2T[jf*64 + fb] = d2T_val;
            }
        }
        gbar(tgt);

        // ---- Phase GRU2 (no trailing global barrier) ----
        {
            const float4* wi = w4s + 2048 + jj*256;
            const float4* wh = w4s + 2560 + jj*256;
            const float2* x2 = (const float2*)d_d2T;
            const float2* h2v = (const float2*)h2o;
            float irA=0,izA=0,inA=0,hrA=0,hzA=0,hnA=0;
            float irB=0,izB=0,inB=0,hrB=0,hzB=0,hnB=0;
            int k = kc*16;
#pragma unroll
            for (int kk = 0; kk < 16; kk++, k++) {
                float4 a = wi[k]; float2 x = x2[k*32 + b2];
                irA += a.x*x.x; izA += a.y*x.x; inA += a.z*x.x;
                irB += a.x*x.y; izB += a.y*x.y; inB += a.z*x.y;
                float4 w = wh[k]; float2 h = h2v[k*32 + b2];
                hrA += w.x*h.x; hzA += w.y*h.x; hnA += w.z*h.x;
                hrB += w.x*h.y; hzB += w.y*h.y; hnB += w.z*h.y;
            }
            int ob = (jj*384 + bb)*17 + kc;
            p6[ob + 0*1088] = irA; p6[ob + 0*1088 + 17] = irB;
            p6[ob + 1*1088] = izA; p6[ob + 1*1088 + 17] = izB;
            p6[ob + 2*1088] = inA; p6[ob + 2*1088 + 17] = inB;
            p6[ob + 3*1088] = hrA; p6[ob + 3*1088 + 17] = hrB;
            p6[ob + 4*1088] = hzA; p6[ob + 4*1088 + 17] = hzB;
            p6[ob + 5*1088] = hnA; p6[ob + 5*1088 + 17] = hnB;
            __syncthreads();
            if (tid < 128) {
                float s0=0,s1=0,s2=0,s3=0,s4=0,s5=0;
                int base = (fjj*384 + fb)*17;
#pragma unroll
                for (int q = 0; q < 16; q++) {
                    s0 += p6[base + q];          s1 += p6[base + 1088 + q];
                    s2 += p6[base + 2176 + q];   s3 += p6[base + 3264 + q];
                    s4 += p6[base + 4352 + q];   s5 += p6[base + 5440 + q];
                }
                float gr = s0 + g2_bih[jf], gz = s1 + g2_bih[256+jf], gn = s2 + g2_bih[512+jf];
                float hr = s3 + g2_bhh[jf], hz = s4 + g2_bhh[256+jf], hn = s5 + g2_bhh[512+jf];
                float r = sigmoidf_(gr + hr), z = sigmoidf_(gz + hz);
                float n = tanhf(gn + r*hn);
                h2_prev = (1.f - z)*n + z*h2_prev;
                h2n[jf*64 + fb] = h2_prev;
                d_pbuf[((size_t)t*512 + jf)*64 + fb] = h2_prev + d2T_val;
            }
            __syncthreads();   // protect p6 reuse at next iteration's Phase A
        }
    }
}

__global__ void post_kernel(const float* __restrict__ mel_w, const float* __restrict__ mel_b,
                            const float* __restrict__ stop_w, const float* __restrict__ stop_b,
                            float* __restrict__ out) {
    int t = blockIdx.x, tid = threadIdx.x;
    __shared__ __align__(16) float p[512];
    float* stop_out = out + 5324800;
    for (int b = 0; b < 64; b++) {
        __syncthreads();
        p[tid]       = d_pbuf[((size_t)t*512 + tid)*64 + b];
        p[tid + 256] = d_pbuf[((size_t)t*512 + tid + 256)*64 + b];
        __syncthreads();
        if (tid < 160) {
            const float4* w4 = (const float4*)(mel_w + (size_t)tid*512);
            const float4* p4 = (const float4*)p;
            float acc = mel_b[tid];
#pragma unroll 8
            for (int i = 0; i < 128; i++) {
                float4 a = w4[i], x = p4[i];
                acc += a.x*x.x + a.y*x.y + a.z*x.z + a.w*x.w;
            }
            out[((size_t)b*TDEC + t)*160 + tid] = acc;
        } else if (tid == 192) {
            float acc = stop_b[0];
            for (int i = 0; i < 512; i++) acc += stop_w[i] * p[i];
            float s = 1.f / (1.f + expf(-acc));
            stop_out[b*400 + 2*t]     = s;
            stop_out[b*400 + 2*t + 1] = s;
        }
    }
}

extern "C" void kernel_launch(void* const* d_in, const int* in_sizes, int n_in,
                              void* d_out, int out_size) {
    const float* enc      = (const float*)d_in[0];
    const float* inputs   = (const float*)d_in[1];
    const int*   memlen   = (const int*)  d_in[2];
    const float* pre_w1   = (const float*)d_in[3];
    const float* pre_b1   = (const float*)d_in[4];
    const float* pre_w2   = (const float*)d_in[5];
    const float* pre_b2   = (const float*)d_in[6];
    const float* mem_w    = (const float*)d_in[7];
    const float* att_wih  = (const float*)d_in[8];
    const float* att_whh  = (const float*)d_in[9];
    const float* att_bih  = (const float*)d_in[10];
    const float* att_bhh  = (const float*)d_in[11];
    const float* q_w      = (const float*)d_in[12];
    const float* v_w      = (const float*)d_in[13];
    const float* proj_w   = (const float*)d_in[14];
    const float* proj_b   = (const float*)d_in[15];
    const float* g1_wih   = (const float*)d_in[16];
    const float* g1_whh   = (const float*)d_in[17];
    const float* g1_bih   = (const float*)d_in[18];
    const float* g1_bhh   = (const float*)d_in[19];
    const float* g2_wih   = (const float*)d_in[20];
    const float* g2_whh   = (const float*)d_in[21];
    const float* g2_bih   = (const float*)d_in[22];
    const float* g2_bhh   = (const float*)d_in[23];
    const float* mel_w    = (const float*)d_in[24];
    const float* mel_b    = (const float*)d_in[25];
    const float* stop_w   = (const float*)d_in[26];
    const float* stop_b   = (const float*)d_in[27];
    float* out = (float*)d_out;

    int smem_bytes = (14592 + 13056) * (int)sizeof(float);   // 110592 B
    static int smem_set = 0;
    if (!smem_set) {
        cudaFuncSetAttribute(loop_kernel, cudaFuncAttributeMaxDynamicSharedMemorySize,
                             smem_bytes);
        smem_set = 1;
    }

    pack_kernel<<<256, 256>>>(att_wih, att_whh, g1_wih, g1_whh, g2_wih, g2_whh);
    pm_kernel<<<16384, 256>>>(enc, mem_w);
    prenet_kernel<<<dim3(TDEC, 64), 256>>>(inputs, pre_w1, pre_b1, pre_w2, pre_b2,
                                           att_wih, att_bih);
    loop_kernel<<<NB, NT, smem_bytes>>>(enc, memlen, att_bhh, q_w, v_w, proj_w, proj_b,
                                        g1_bih, g1_bhh, g2_bih, g2_bhh, out);
    post_kernel<<<TDEC, 256>>>(mel_w, mel_b, stop_w, stop_b, out);
}